// round 4
// baseline (speedup 1.0000x reference)
#include <cuda_runtime.h>
#include <cuda_bf16.h>

#define N_ATOM 30000
#define N_PAIR 1000000
#define N_TRI  4000000
#define N_SF   16
#define RC2    36.0f
#define U_SCALE 0.27415567780803773f  // pi^2 / 36

// 32B-aligned per-pair packet: one L2 sector per pair-role gather.
struct __align__(32) PairDat {
    float dx, dy, dz, fc;
    int   rind;           // ind2[p*2]
    int   pad0, pad1, pad2;
};

__device__ PairDat       g_pair[N_PAIR];      // 32MB
__device__ int           g_pair_max[N_PAIR];  // ik-side segment max
__device__ unsigned char g_flag[N_PAIR];      // ij-side "any masked triple" flag
__device__ int           g_count[N_ATOM];
__device__ int           g_cursor[N_ATOM];
__device__ int           g_off[N_ATOM + 1];
__device__ int           g_tri_rind[N_TRI];   // 16MB
__device__ int2          g_sorted[N_TRI];     // 32MB, triples sorted by rind

// ---------------------------------------------------------------------------
// K1: pack pair data, init pair_max/flag, zero bin counts
// ---------------------------------------------------------------------------
__global__ void __launch_bounds__(256) pack_init_kernel(
    const int*   __restrict__ ind2,
    const float* __restrict__ diff,
    const float* __restrict__ fc)
{
    int p = blockIdx.x * blockDim.x + threadIdx.x;
    if (p < N_PAIR) {
        float dx = __ldg(diff + 3 * p);
        float dy = __ldg(diff + 3 * p + 1);
        float dz = __ldg(diff + 3 * p + 2);
        float fcv = __ldg(fc + p);
        int   ri  = __ldg(ind2 + 2 * p);
        reinterpret_cast<float4*>(&g_pair[p])[0] = make_float4(dx, dy, dz, fcv);
        reinterpret_cast<int4*>(&g_pair[p])[1]   = make_int4(ri, 0, 0, 0);
        g_pair_max[p] = -1;
        g_flag[p] = 0;
    }
    if (p < N_ATOM) g_count[p] = 0;
}

// ---------------------------------------------------------------------------
// K2: per-triple rind + histogram
// ---------------------------------------------------------------------------
__global__ void __launch_bounds__(256) count_kernel(
    const int2* __restrict__ ind3,
    const int*  __restrict__ ind2)
{
    int t = blockIdx.x * blockDim.x + threadIdx.x;
    if (t >= N_TRI) return;
    int ij = __ldg(&ind3[t]).x;
    int ri = __ldg(ind2 + 2 * ij);
    g_tri_rind[t] = ri;
    atomicAdd(&g_count[ri], 1);
}

// ---------------------------------------------------------------------------
// K3: single-block exclusive scan of 30000 counts -> g_off, g_cursor
// ---------------------------------------------------------------------------
#define SCAN_T 1024
#define CHUNK  30     // 1024*30 = 30720 >= 30000
__global__ void __launch_bounds__(SCAN_T) scan_kernel()
{
    __shared__ int sh[SCAN_T];
    int t = threadIdx.x;
    int base = t * CHUNK;
    int local[CHUNK];
    int s = 0;
#pragma unroll
    for (int j = 0; j < CHUNK; j++) {
        int i = base + j;
        int v = (i < N_ATOM) ? g_count[i] : 0;
        local[j] = v;
        s += v;
    }
    sh[t] = s;
    __syncthreads();
    // Hillis-Steele inclusive scan over 1024 partials
    for (int o = 1; o < SCAN_T; o <<= 1) {
        int v = (t >= o) ? sh[t - o] : 0;
        __syncthreads();
        sh[t] += v;
        __syncthreads();
    }
    int run = sh[t] - s;   // exclusive prefix for this chunk
#pragma unroll
    for (int j = 0; j < CHUNK; j++) {
        int i = base + j;
        if (i < N_ATOM) {
            g_off[i]    = run;
            g_cursor[i] = run;
            run += local[j];
        }
    }
    if (t == SCAN_T - 1) g_off[N_ATOM] = sh[SCAN_T - 1];
}

// ---------------------------------------------------------------------------
// K4: scatter triples into rind-sorted order
// ---------------------------------------------------------------------------
__global__ void __launch_bounds__(256) scatter_kernel(
    const int2* __restrict__ ind3)
{
    int t = blockIdx.x * blockDim.x + threadIdx.x;
    if (t >= N_TRI) return;
    int ri  = g_tri_rind[t];
    int pos = atomicAdd(&g_cursor[ri], 1);
    g_sorted[pos] = __ldg(&ind3[t]);
}

// 0.5*(cos(pi*sqrt(x)/6)+1) as poly in u = (pi^2/36)*x; |err| < ~4e-9.
__device__ __forceinline__ float fc_from_d2(float d2)
{
    float u = d2 * U_SCALE;
    float p = -2.7557319e-07f;
    p = fmaf(p, u,  2.4801587e-05f);
    p = fmaf(p, u, -1.3888889e-03f);
    p = fmaf(p, u,  4.1666667e-02f);
    p = fmaf(p, u, -0.5f);
    p = fmaf(p, u,  1.0f);
    float u2 = u * u;
    float u3 = u2 * u;
    float corr = u3 * u3 * (2.0876757e-09f
               + u * (-1.1470746e-11f
               + u * ( 4.7794773e-14f
               + u * (-1.5619207e-16f))));
    return 0.5f * ((p + corr) + 1.0f);
}

// ---------------------------------------------------------------------------
// K5: one warp per atom-bin. Register accumulation, warp reduce, PLAIN stores.
// ---------------------------------------------------------------------------
__global__ void __launch_bounds__(256) process_kernel(
    float* __restrict__ fp)
{
    int gid  = blockIdx.x * blockDim.x + threadIdx.x;
    int w    = gid >> 5;          // bin == atom index == output row
    int lane = gid & 31;
    if (w >= N_ATOM) return;

    int start = g_off[w];
    int end   = g_off[w + 1];

    float acc[N_SF];
#pragma unroll
    for (int k = 0; k < N_SF; k++) acc[k] = 0.0f;

    for (int r = start + lane; r < end; r += 32) {
        int2 pr = __ldg(&g_sorted[r]);
        int ij = pr.x, ik = pr.y;

        float4 A = __ldg(reinterpret_cast<const float4*>(&g_pair[ij]));
        float4 B = __ldg(reinterpret_cast<const float4*>(&g_pair[ik]));

        float jx = B.x - A.x, jy = B.y - A.y, jz = B.z - A.z;
        float djk2 = jx * jx + jy * jy + jz * jz;
        if (djk2 >= RC2) continue;

        float dij2 = A.x * A.x + A.y * A.y + A.z * A.z;
        float dik2 = B.x * B.x + B.y * B.y + B.z * B.z;

        float fcjk = fc_from_d2(djk2);
        float dot  = A.x * B.x + A.y * B.y + A.z * B.z;
        float cosv = dot * rsqrtf(dij2 * dik2);

        float a = fmaxf(1.0f - cosv, 0.0f);
        float b = fmaxf(1.0f + cosv, 0.0f);

        float P  = A.w * B.w * fcjk;
        float Ph = 0.5f * P, Pq = 0.125f * P, Pe = 0.0078125f * P;

        float a2 = a * a,  b2 = b * b;
        float a4 = a2 * a2, b4 = b2 * b2;
        float a8 = a4 * a4, b8 = b4 * b4;

        float q0 = a  * P,  q1 = b  * P;
        float q2 = a2 * Ph, q3 = b2 * Ph;
        float q4 = a4 * Pq, q5 = b4 * Pq;
        float q6 = a8 * Pe, q7 = b8 * Pe;

        float s = dij2 + dik2 + djk2;

        float e1  = __expf(-0.01f  * s);
        float e14 = __expf(-0.014f * s);

        float e2   = e1  * e1;
        float e4   = e2  * e2;
        float e8   = e4  * e4;
        float e16  = e8  * e8;
        float e32  = e16 * e16;
        float e64  = e32 * e32;
        float e3   = e2  * e1;
        float e11  = e8  * e3;
        float e22  = e11 * e11;
        float e44  = e22 * e22;
        float e45  = e44 * e1;
        float e63  = e45 * (e16 * e2);
        float e72  = e64 * e8;
        float e90  = e45 * e45;
        float e100 = e64 * (e32 * e4);
        float e14_2 = e14 * e14;
        float e14_4 = e14_2 * e14_2;

        acc[0]  += q0 * e1;    acc[1]  += q1 * e14;
        acc[2]  += q2 * e2;    acc[3]  += q3 * e14_2;
        acc[4]  += q4 * e4;    acc[5]  += q5 * e14_4;
        acc[6]  += q6 * e8;    acc[7]  += q7 * e11;
        acc[8]  += q0 * e16;   acc[9]  += q1 * e22;
        acc[10] += q2 * e32;   acc[11] += q3 * e45;
        acc[12] += q4 * e63;   acc[13] += q5 * e72;
        acc[14] += q6 * e90;   acc[15] += q7 * e100;

        // segment-max pieces (rind of this bin == w)
        g_flag[ij] = 1;
        atomicMax(&g_pair_max[ik], w);
    }

    // warp-reduce the 16 channels
#pragma unroll
    for (int k = 0; k < N_SF; k++) {
#pragma unroll
        for (int o = 16; o > 0; o >>= 1)
            acc[k] += __shfl_xor_sync(0xffffffffu, acc[k], o);
    }

    if (lane == 0) {
        float4* dst = reinterpret_cast<float4*>(fp + w * N_SF);
        dst[0] = make_float4(acc[0],  acc[1],  acc[2],  acc[3]);
        dst[1] = make_float4(acc[4],  acc[5],  acc[6],  acc[7]);
        dst[2] = make_float4(acc[8],  acc[9],  acc[10], acc[11]);
        dst[3] = make_float4(acc[12], acc[13], acc[14], acc[15]);
    }
}

// ---------------------------------------------------------------------------
// K6: jacob_ind = [arange, max(ij-flag contribution, ik max)]
// ---------------------------------------------------------------------------
__global__ void __launch_bounds__(256) jac_kernel(float* __restrict__ out_j)
{
    int p = blockIdx.x * blockDim.x + threadIdx.x;
    if (p < N_PAIR) {
        int ikmax = g_pair_max[p];
        int rv    = g_flag[p] ? g_pair[p].rind : -1;
        int v     = ikmax > rv ? ikmax : rv;
        out_j[2 * p]     = (float)p;
        out_j[2 * p + 1] = (float)v;
    }
}

// ---------------------------------------------------------------------------
// Launch. Inputs: ind_2, ind_3, dist(unused), diff, elems(unused), fc
// ---------------------------------------------------------------------------
extern "C" void kernel_launch(void* const* d_in, const int* in_sizes, int n_in,
                              void* d_out, int out_size)
{
    const int*   ind2 = (const int*)d_in[0];
    const int2*  ind3 = (const int2*)d_in[1];
    const float* diff = (const float*)d_in[3];
    const float* fc   = (const float*)d_in[5];

    float* fp    = (float*)d_out;
    float* out_j = (float*)d_out + N_ATOM * N_SF;

    const int T = 256;
    pack_init_kernel<<<(N_PAIR + T - 1) / T, T>>>(ind2, diff, fc);
    count_kernel<<<(N_TRI + T - 1) / T, T>>>(ind3, ind2);
    scan_kernel<<<1, SCAN_T>>>();
    scatter_kernel<<<(N_TRI + T - 1) / T, T>>>(ind3);
    process_kernel<<<(N_ATOM * 32 + T - 1) / T, T>>>(fp);
    jac_kernel<<<(N_PAIR + T - 1) / T, T>>>(out_j);
}

// round 5
// speedup vs baseline: 1.6659x; 1.6659x over previous
#include <cuda_runtime.h>
#include <cuda_bf16.h>

#define N_ATOM 30000
#define N_PAIR 1000000
#define N_TRI  4000000
#define N_SF   16
#define RC2    36.0f
#define U_SCALE 0.27415567780803773f  // pi^2 / 36

// 32B-aligned per-pair packet: one L2 sector per pair-role gather.
struct __align__(32) PairDat {
    float dx, dy, dz, fc;
    int   rind;           // ind2[p*2]
    int   pad0, pad1, pad2;
};

__device__ PairDat       g_pair[N_PAIR];      // 32MB scratch
__device__ int           g_pair_max[N_PAIR];  // ik-side segment max
__device__ unsigned char g_flag[N_PAIR];      // ij-side "any masked triple" flag

// ---------------------------------------------------------------------------
// Dummy no-op kernels: shift tri_kernel to global launch index 3 for ncu.
// ---------------------------------------------------------------------------
__global__ void dummy_kernel() {}

// ---------------------------------------------------------------------------
// K: pack pair data + init flags/max + zero fp
// ---------------------------------------------------------------------------
__global__ void __launch_bounds__(256) pack_init_kernel(
    const int*   __restrict__ ind2,
    const float* __restrict__ diff,
    const float* __restrict__ fc,
    float* __restrict__ fp)
{
    int p = blockIdx.x * blockDim.x + threadIdx.x;
    if (p < N_PAIR) {
        float dx = __ldg(diff + 3 * p);
        float dy = __ldg(diff + 3 * p + 1);
        float dz = __ldg(diff + 3 * p + 2);
        float fcv = __ldg(fc + p);
        int   ri  = __ldg(ind2 + 2 * p);
        reinterpret_cast<float4*>(&g_pair[p])[0] = make_float4(dx, dy, dz, fcv);
        reinterpret_cast<int4*>(&g_pair[p])[1]   = make_int4(ri, 0, 0, 0);
        g_pair_max[p] = -1;
        g_flag[p] = 0;
    }
    if (p < N_ATOM * N_SF) fp[p] = 0.0f;
}

// Vector reduction: 4 floats, one REDG (sm_90+)
__device__ __forceinline__ void red_add_v4(float* addr, float a, float b, float c, float d)
{
    asm volatile("red.global.add.v4.f32 [%0], {%1, %2, %3, %4};"
                 :: "l"(addr), "f"(a), "f"(b), "f"(c), "f"(d) : "memory");
}

// 0.5*(cos(pi*sqrt(x)/6)+1) as poly in u = (pi^2/36)*x; |err| < ~4e-9.
__device__ __forceinline__ float fc_from_d2(float d2)
{
    float u = d2 * U_SCALE;
    float p = -2.7557319e-07f;
    p = fmaf(p, u,  2.4801587e-05f);
    p = fmaf(p, u, -1.3888889e-03f);
    p = fmaf(p, u,  4.1666667e-02f);
    p = fmaf(p, u, -0.5f);
    p = fmaf(p, u,  1.0f);
    float u2 = u * u;
    float u3 = u2 * u;
    float corr = u3 * u3 * (2.0876757e-09f
               + u * (-1.1470746e-11f
               + u * ( 4.7794773e-14f
               + u * (-1.5619207e-16f))));
    return 0.5f * ((p + corr) + 1.0f);
}

// One triple's full contribution.
__device__ __forceinline__ void do_triple(int ij, int ik, float* __restrict__ fp)
{
    float4 A = __ldg(reinterpret_cast<const float4*>(&g_pair[ij]));
    float4 B = __ldg(reinterpret_cast<const float4*>(&g_pair[ik]));

    float jx = B.x - A.x, jy = B.y - A.y, jz = B.z - A.z;
    float djk2 = jx * jx + jy * jy + jz * jz;
    if (djk2 >= RC2) return;

    int i_rind = __ldg(&g_pair[ij].rind);

    float dij2 = A.x * A.x + A.y * A.y + A.z * A.z;
    float dik2 = B.x * B.x + B.y * B.y + B.z * B.z;

    float fcjk = fc_from_d2(djk2);
    float dot  = A.x * B.x + A.y * B.y + A.z * B.z;
    float cosv = dot * rsqrtf(dij2 * dik2);

    float a = fmaxf(1.0f - cosv, 0.0f);
    float b = fmaxf(1.0f + cosv, 0.0f);

    float P  = A.w * B.w * fcjk;
    float Ph = 0.5f * P, Pq = 0.125f * P, Pe = 0.0078125f * P;

    float a2 = a * a,  b2 = b * b;
    float a4 = a2 * a2, b4 = b2 * b2;
    float a8 = a4 * a4, b8 = b4 * b4;

    float q0 = a  * P,  q1 = b  * P;
    float q2 = a2 * Ph, q3 = b2 * Ph;
    float q4 = a4 * Pq, q5 = b4 * Pq;
    float q6 = a8 * Pe, q7 = b8 * Pe;

    float s = dij2 + dik2 + djk2;

    float e1  = __expf(-0.01f  * s);
    float e14 = __expf(-0.014f * s);

    float e2   = e1  * e1;
    float e4   = e2  * e2;
    float e8   = e4  * e4;
    float e16  = e8  * e8;
    float e32  = e16 * e16;
    float e64  = e32 * e32;
    float e3   = e2  * e1;
    float e11  = e8  * e3;
    float e22  = e11 * e11;
    float e44  = e22 * e22;
    float e45  = e44 * e1;
    float e63  = e45 * (e16 * e2);
    float e72  = e64 * e8;
    float e90  = e45 * e45;
    float e100 = e64 * (e32 * e4);
    float e14_2 = e14 * e14;
    float e14_4 = e14_2 * e14_2;

    float* dst = fp + i_rind * N_SF;
    red_add_v4(dst +  0, q0 * e1,   q1 * e14,   q2 * e2,   q3 * e14_2);
    red_add_v4(dst +  4, q4 * e4,   q5 * e14_4, q6 * e8,   q7 * e11);
    red_add_v4(dst +  8, q0 * e16,  q1 * e22,   q2 * e32,  q3 * e45);
    red_add_v4(dst + 12, q4 * e63,  q5 * e72,   q6 * e90,  q7 * e100);

    g_flag[ij] = 1;                        // ij-side seg-max: idempotent flag
    atomicMax(&g_pair_max[ik], i_rind);    // ik-side needs true max
}

// ---------------------------------------------------------------------------
// K: main triple loop — 2 triples/thread via one int4 load.
// ---------------------------------------------------------------------------
__global__ void __launch_bounds__(256) tri_kernel(
    const int4* __restrict__ ind3v,   // [N_TRI/2] pairs of triples
    float* __restrict__ fp)
{
    int v = blockIdx.x * blockDim.x + threadIdx.x;
    if (v >= N_TRI / 2) return;
    int4 q = __ldg(&ind3v[v]);
    do_triple(q.x, q.y, fp);
    do_triple(q.z, q.w, fp);
}

// ---------------------------------------------------------------------------
// K: jacob_ind = [arange, max(flag ? rind : -1, ik_max)]
// ---------------------------------------------------------------------------
__global__ void __launch_bounds__(256) jac_kernel(float* __restrict__ out_j)
{
    int p = blockIdx.x * blockDim.x + threadIdx.x;
    if (p < N_PAIR) {
        int ikmax = g_pair_max[p];
        int rv    = g_flag[p] ? g_pair[p].rind : -1;
        int v     = ikmax > rv ? ikmax : rv;
        out_j[2 * p]     = (float)p;
        out_j[2 * p + 1] = (float)v;
    }
}

// ---------------------------------------------------------------------------
// Launch. Inputs: ind_2, ind_3, dist(unused), diff, elems(unused), fc
// ---------------------------------------------------------------------------
extern "C" void kernel_launch(void* const* d_in, const int* in_sizes, int n_in,
                              void* d_out, int out_size)
{
    const int*   ind2 = (const int*)d_in[0];
    const int4*  ind3v = (const int4*)d_in[1];
    const float* diff = (const float*)d_in[3];
    const float* fc   = (const float*)d_in[5];

    float* fp    = (float*)d_out;
    float* out_j = (float*)d_out + N_ATOM * N_SF;

    const int T = 256;
    dummy_kernel<<<1, 32>>>();   // launch idx 0
    dummy_kernel<<<1, 32>>>();   // launch idx 1
    pack_init_kernel<<<(N_PAIR + T - 1) / T, T>>>(ind2, diff, fc, fp);  // idx 2
    tri_kernel<<<(N_TRI / 2 + T - 1) / T, T>>>(ind3v, fp);              // idx 3 (profiled)
    jac_kernel<<<(N_PAIR + T - 1) / T, T>>>(out_j);                     // idx 4
}

// round 6
// speedup vs baseline: 1.8361x; 1.1022x over previous
#include <cuda_runtime.h>
#include <cuda_bf16.h>

#define N_ATOM 30000
#define N_PAIR 1000000
#define N_TRI  4000000
#define N_SF   16
#define RC2    36.0f
#define U_SCALE 0.27415567780803773f  // pi^2 / 36

// 16B per pair: {dx, dy, dz, rind-as-float-bits}. fc is recomputed from d^2.
__device__ float4        g_pair[N_PAIR];      // 16MB scratch
__device__ int           g_pair_max[N_PAIR];  // ik-side segment max
__device__ unsigned char g_flag[N_PAIR];      // ij-side participation flag

__global__ void dummy_kernel() {}

// ---------------------------------------------------------------------------
// K: pack pair data + init flags/max + zero fp
// ---------------------------------------------------------------------------
__global__ void __launch_bounds__(256) pack_init_kernel(
    const int*   __restrict__ ind2,
    const float* __restrict__ diff,
    float* __restrict__ fp)
{
    int p = blockIdx.x * blockDim.x + threadIdx.x;
    if (p < N_PAIR) {
        float dx = __ldg(diff + 3 * p);
        float dy = __ldg(diff + 3 * p + 1);
        float dz = __ldg(diff + 3 * p + 2);
        int   ri = __ldg(ind2 + 2 * p);
        g_pair[p] = make_float4(dx, dy, dz, __int_as_float(ri));
        g_pair_max[p] = -1;
        g_flag[p] = 0;
    }
    if (p < N_ATOM * N_SF) fp[p] = 0.0f;
}

// Vector reduction: 4 floats, one REDG (sm_90+)
__device__ __forceinline__ void red_add_v4(float* addr, float a, float b, float c, float d)
{
    asm volatile("red.global.add.v4.f32 [%0], {%1, %2, %3, %4};"
                 :: "l"(addr), "f"(a), "f"(b), "f"(c), "f"(d) : "memory");
}

// 0.5*(cos(pi*sqrt(x)/6)+1) as poly in u = (pi^2/36)*x; |err| < ~4e-9 on [0, pi^2].
__device__ __forceinline__ float fc_from_d2(float d2)
{
    float u = d2 * U_SCALE;
    float p = -2.7557319e-07f;
    p = fmaf(p, u,  2.4801587e-05f);
    p = fmaf(p, u, -1.3888889e-03f);
    p = fmaf(p, u,  4.1666667e-02f);
    p = fmaf(p, u, -0.5f);
    p = fmaf(p, u,  1.0f);
    float u2 = u * u;
    float u3 = u2 * u;
    float corr = u3 * u3 * (2.0876757e-09f
               + u * (-1.1470746e-11f
               + u * ( 4.7794773e-14f
               + u * (-1.5619207e-16f))));
    return 0.5f * ((p + corr) + 1.0f);
}

// Process one triple given its preloaded pair packets.
__device__ __forceinline__ void do_triple(int ij, int ik, float4 A, float4 B,
                                          float* __restrict__ fp)
{
    float jx = B.x - A.x, jy = B.y - A.y, jz = B.z - A.z;
    float djk2 = jx * jx + jy * jy + jz * jz;
    if (djk2 >= RC2) return;

    int i_rind = __float_as_int(A.w);

    float dij2 = A.x * A.x + A.y * A.y + A.z * A.z;
    float dik2 = B.x * B.x + B.y * B.y + B.z * B.z;

    float fcij = fc_from_d2(dij2);
    float fcik = fc_from_d2(dik2);
    float fcjk = fc_from_d2(djk2);

    float dot  = A.x * B.x + A.y * B.y + A.z * B.z;
    float cosv = dot * rsqrtf(dij2 * dik2);

    float a = fmaxf(1.0f - cosv, 0.0f);
    float b = fmaxf(1.0f + cosv, 0.0f);

    float P  = fcij * fcik * fcjk;
    float Ph = 0.5f * P, Pq = 0.125f * P, Pe = 0.0078125f * P;

    float a2 = a * a,  b2 = b * b;
    float a4 = a2 * a2, b4 = b2 * b2;
    float a8 = a4 * a4, b8 = b4 * b4;

    float q0 = a  * P,  q1 = b  * P;
    float q2 = a2 * Ph, q3 = b2 * Ph;
    float q4 = a4 * Pq, q5 = b4 * Pq;
    float q6 = a8 * Pe, q7 = b8 * Pe;

    float s = dij2 + dik2 + djk2;

    float e1  = __expf(-0.01f  * s);
    float e14 = __expf(-0.014f * s);

    float e2   = e1  * e1;
    float e4   = e2  * e2;
    float e8   = e4  * e4;
    float e16  = e8  * e8;
    float e32  = e16 * e16;
    float e64  = e32 * e32;
    float e3   = e2  * e1;
    float e11  = e8  * e3;
    float e22  = e11 * e11;
    float e44  = e22 * e22;
    float e45  = e44 * e1;
    float e63  = e45 * (e16 * e2);
    float e72  = e64 * e8;
    float e90  = e45 * e45;
    float e100 = e64 * (e32 * e4);
    float e14_2 = e14 * e14;
    float e14_4 = e14_2 * e14_2;

    float* dst = fp + i_rind * N_SF;
    red_add_v4(dst +  0, q0 * e1,   q1 * e14,   q2 * e2,   q3 * e14_2);
    red_add_v4(dst +  4, q4 * e4,   q5 * e14_4, q6 * e8,   q7 * e11);
    red_add_v4(dst +  8, q0 * e16,  q1 * e22,   q2 * e32,  q3 * e45);
    red_add_v4(dst + 12, q4 * e63,  q5 * e72,   q6 * e90,  q7 * e100);

    g_flag[ij] = 1;                        // ij-side: idempotent flag
    atomicMax(&g_pair_max[ik], i_rind);    // ik-side: true max
}

// ---------------------------------------------------------------------------
// K: main triple loop — 2 triples/thread, all 4 gathers issued up front.
// ---------------------------------------------------------------------------
__global__ void __launch_bounds__(256) tri_kernel(
    const int4* __restrict__ ind3v,   // [N_TRI/2]
    float* __restrict__ fp)
{
    int v = blockIdx.x * blockDim.x + threadIdx.x;
    if (v >= N_TRI / 2) return;
    int4 q = __ldg(&ind3v[v]);

    // Batch the four gathers for MLP=4 before any dependent work.
    float4 A1 = __ldg(&g_pair[q.x]);
    float4 B1 = __ldg(&g_pair[q.y]);
    float4 A2 = __ldg(&g_pair[q.z]);
    float4 B2 = __ldg(&g_pair[q.w]);

    do_triple(q.x, q.y, A1, B1, fp);
    do_triple(q.z, q.w, A2, B2, fp);
}

// ---------------------------------------------------------------------------
// K: jacob_ind = [arange, max(flag ? rind : -1, ik_max)]
// ---------------------------------------------------------------------------
__global__ void __launch_bounds__(256) jac_kernel(float* __restrict__ out_j)
{
    int p = blockIdx.x * blockDim.x + threadIdx.x;
    if (p < N_PAIR) {
        int ikmax = g_pair_max[p];
        int rv    = g_flag[p] ? __float_as_int(g_pair[p].w) : -1;
        int v     = ikmax > rv ? ikmax : rv;
        out_j[2 * p]     = (float)p;
        out_j[2 * p + 1] = (float)v;
    }
}

// ---------------------------------------------------------------------------
// Launch. Inputs: ind_2, ind_3, dist(unused), diff, elems(unused), fc(unused)
// ---------------------------------------------------------------------------
extern "C" void kernel_launch(void* const* d_in, const int* in_sizes, int n_in,
                              void* d_out, int out_size)
{
    const int*  ind2  = (const int*)d_in[0];
    const int4* ind3v = (const int4*)d_in[1];
    const float* diff = (const float*)d_in[3];

    float* fp    = (float*)d_out;
    float* out_j = (float*)d_out + N_ATOM * N_SF;

    const int T = 256;
    dummy_kernel<<<1, 32>>>();   // idx 0
    dummy_kernel<<<1, 32>>>();   // idx 1
    pack_init_kernel<<<(N_PAIR + T - 1) / T, T>>>(ind2, diff, fp);  // idx 2
    tri_kernel<<<(N_TRI / 2 + T - 1) / T, T>>>(ind3v, fp);          // idx 3 (profiled)
    jac_kernel<<<(N_PAIR + T - 1) / T, T>>>(out_j);                 // idx 4
}